// round 4
// baseline (speedup 1.0000x reference)
#include <cuda_runtime.h>

#define MAXN 100000
#define MAXE 1600000

// Scratch (device globals — no allocation allowed)
__device__ float g_deg[MAXN];
__device__ float g_dinv[MAXN];
__device__ float g_h1[(size_t)MAXN * 64];   // X@W1, later relu output
__device__ float g_o1[(size_t)MAXN * 64];   // layer-1 accumulator
__device__ float g_h3[(size_t)MAXN * 40];   // h2@W2
__device__ int   g_src[MAXE];
__device__ int   g_dst[MAXE];
__device__ float g_nrm[MAXE];

__global__ void zero_deg_k(int n) {
    int i = blockIdx.x * blockDim.x + threadIdx.x;
    if (i < n) g_deg[i] = 0.f;
}

// degree over dst (self-loop handled as +1 in dinv kernel).
// edge_index is INT32 (JAX default x64-disabled downcasts the reference's
// "int64" to int32). Guard keeps any surprise in-bounds.
__global__ void deg_k(const int* __restrict__ ei, int E, int N) {
    int i = blockIdx.x * blockDim.x + threadIdx.x;
    if (i >= E) return;
    int d = ei[E + i];
    if ((unsigned)d < (unsigned)N) atomicAdd(g_deg + d, 1.0f);
}

__global__ void dinv_k(int N) {
    int i = blockIdx.x * blockDim.x + threadIdx.x;
    if (i < N) g_dinv[i] = rsqrtf(g_deg[i] + 1.0f);  // +1 = self loop; > 0 always
}

// compact edges + precomputed per-edge norm (guarded)
__global__ void prep_k(const int* __restrict__ ei, int E, int N) {
    int i = blockIdx.x * blockDim.x + threadIdx.x;
    if (i >= E) return;
    int s = ei[i];
    int d = ei[E + i];
    bool ok = ((unsigned)s < (unsigned)N) && ((unsigned)d < (unsigned)N);
    g_src[i] = ok ? s : 0;
    g_dst[i] = ok ? d : 0;
    g_nrm[i] = ok ? g_dinv[s] * g_dinv[d] : 0.f;
}

// ---------------- GEMM layer 1: g_h1 = X @ W1 ; g_o1 = g_h1 * dinv^2 --------
__global__ __launch_bounds__(256) void gemm1_k(
    const float* __restrict__ X, const float* __restrict__ W, int N)
{
    __shared__ float Ws[128 * 64];
    for (int i = threadIdx.x; i < 128 * 64; i += 256) Ws[i] = W[i];
    __syncthreads();

    int r = blockIdx.x * 256 + threadIdx.x;
    if (r >= N) return;

    float acc[64];
#pragma unroll
    for (int j = 0; j < 64; j++) acc[j] = 0.f;

    const float4* xr = (const float4*)(X + (size_t)r * 128);
#pragma unroll 1
    for (int k4 = 0; k4 < 32; k4++) {
        float4 xv = xr[k4];
        const float* w0 = Ws + (k4 * 4) * 64;
#pragma unroll
        for (int j = 0; j < 64; j++)
            acc[j] += xv.x * w0[j] + xv.y * w0[64 + j] + xv.z * w0[128 + j] + xv.w * w0[192 + j];
    }

    float dv = g_dinv[r];
    float sl = dv * dv;
    float4* Hp = (float4*)(g_h1 + (size_t)r * 64);
    float4* Op = (float4*)(g_o1 + (size_t)r * 64);
#pragma unroll
    for (int j4 = 0; j4 < 16; j4++) {
        float4 hv = make_float4(acc[4*j4], acc[4*j4+1], acc[4*j4+2], acc[4*j4+3]);
        Hp[j4] = hv;
        Op[j4] = make_float4(hv.x * sl, hv.y * sl, hv.z * sl, hv.w * sl);
    }
}

// ---------------- GEMM layer 2: g_h3 = h2 @ W2 ; OUT init = g_h3 * dinv^2 ---
__global__ __launch_bounds__(256) void gemm2_k(float* __restrict__ OUT,
                                               const float* __restrict__ W, int N)
{
    __shared__ float Ws[64 * 40];
    for (int i = threadIdx.x; i < 64 * 40; i += 256) Ws[i] = W[i];
    __syncthreads();

    int r = blockIdx.x * 256 + threadIdx.x;
    if (r >= N) return;

    float acc[40];
#pragma unroll
    for (int j = 0; j < 40; j++) acc[j] = 0.f;

    const float4* xr = (const float4*)(g_h1 + (size_t)r * 64);
#pragma unroll 1
    for (int k4 = 0; k4 < 16; k4++) {
        float4 xv = xr[k4];
        const float* w0 = Ws + (k4 * 4) * 40;
#pragma unroll
        for (int j = 0; j < 40; j++)
            acc[j] += xv.x * w0[j] + xv.y * w0[40 + j] + xv.z * w0[80 + j] + xv.w * w0[120 + j];
    }

    float dv = g_dinv[r];
    float sl = dv * dv;
    float4* Hp = (float4*)(g_h3 + (size_t)r * 40);
    float4* Op = (float4*)(OUT + (size_t)r * 40);
#pragma unroll
    for (int j4 = 0; j4 < 10; j4++) {
        float4 hv = make_float4(acc[4*j4], acc[4*j4+1], acc[4*j4+2], acc[4*j4+3]);
        Hp[j4] = hv;
        Op[j4] = make_float4(hv.x * sl, hv.y * sl, hv.z * sl, hv.w * sl);
    }
}

// ---------------- Edge scatter layer 1: g_o1[dst] += g_h1[src] * norm -------
// 16 threads per edge, one float4 chunk each -> 4 scalar fire-and-forget REDs.
__global__ void scatter1_k(int E)
{
    long long t = (long long)blockIdx.x * blockDim.x + threadIdx.x;
    int e = (int)(t >> 4);
    int c = (int)(t & 15);
    if (e >= E) return;
    int s = g_src[e];
    int d = g_dst[e];
    float nv = g_nrm[e];
    float4 v = ((const float4*)(g_h1 + (size_t)s * 64))[c];
    float* p = g_o1 + (size_t)d * 64 + c * 4;
    atomicAdd(p + 0, v.x * nv);
    atomicAdd(p + 1, v.y * nv);
    atomicAdd(p + 2, v.z * nv);
    atomicAdd(p + 3, v.w * nv);
}

// ---------------- Edge scatter layer 2: OUT[dst] += g_h3[src] * norm --------
__global__ void scatter2_k(float* __restrict__ OUT, int E)
{
    long long t = (long long)blockIdx.x * blockDim.x + threadIdx.x;
    int e = (int)(t / 10);
    int c = (int)(t - e * 10);
    if (e >= E) return;
    int s = g_src[e];
    int d = g_dst[e];
    float nv = g_nrm[e];
    float4 v = ((const float4*)(g_h3 + (size_t)s * 40))[c];
    float* p = OUT + (size_t)d * 40 + c * 4;
    atomicAdd(p + 0, v.x * nv);
    atomicAdd(p + 1, v.y * nv);
    atomicAdd(p + 2, v.z * nv);
    atomicAdd(p + 3, v.w * nv);
}

// h2 = relu(o1 + b1) -> stored into g_h1 (64 feats = 16 float4/row)
__global__ void relu_k(const float* __restrict__ b, int n4) {
    int i = blockIdx.x * blockDim.x + threadIdx.x;
    if (i >= n4) return;
    float4 t = ((const float4*)g_o1)[i];
    float4 bb = ((const float4*)b)[i & 15];
    ((float4*)g_h1)[i] = make_float4(fmaxf(t.x + bb.x, 0.f), fmaxf(t.y + bb.y, 0.f),
                                     fmaxf(t.z + bb.z, 0.f), fmaxf(t.w + bb.w, 0.f));
}

// out = log_softmax(out + b2) over 40 classes, one row per thread
__global__ void finish_k(float* __restrict__ out, const float* __restrict__ b, int N) {
    int r = blockIdx.x * blockDim.x + threadIdx.x;
    if (r >= N) return;
    float v[40];
    float4* p = (float4*)(out + (size_t)r * 40);
#pragma unroll
    for (int j4 = 0; j4 < 10; j4++) {
        float4 t = p[j4];
        float4 bb = ((const float4*)b)[j4];
        v[4*j4+0] = t.x + bb.x; v[4*j4+1] = t.y + bb.y;
        v[4*j4+2] = t.z + bb.z; v[4*j4+3] = t.w + bb.w;
    }
    float mx = v[0];
#pragma unroll
    for (int j = 1; j < 40; j++) mx = fmaxf(mx, v[j]);
    float s = 0.f;
#pragma unroll
    for (int j = 0; j < 40; j++) s += expf(v[j] - mx);
    float lse = mx + logf(s);
#pragma unroll
    for (int j4 = 0; j4 < 10; j4++)
        p[j4] = make_float4(v[4*j4] - lse, v[4*j4+1] - lse,
                            v[4*j4+2] - lse, v[4*j4+3] - lse);
}

extern "C" void kernel_launch(void* const* d_in, const int* in_sizes, int n_in,
                              void* d_out, int out_size)
{
    const float* x  = (const float*)d_in[0];
    const int*   ei = (const int*)d_in[1];      // int32! (JAX x64 disabled)
    const float* W1 = (const float*)d_in[2];
    const float* b1 = (const float*)d_in[3];
    const float* W2 = (const float*)d_in[4];
    const float* b2 = (const float*)d_in[5];
    float* out = (float*)d_out;

    int N = in_sizes[0] / 128;
    int E = in_sizes[1] / 2;

    const int T = 256;
    // 1. degrees + norms
    zero_deg_k<<<(N + T - 1) / T, T>>>(N);
    deg_k<<<(E + T - 1) / T, T>>>(ei, E, N);
    dinv_k<<<(N + T - 1) / T, T>>>(N);
    prep_k<<<(E + T - 1) / T, T>>>(ei, E, N);

    // 2. layer 1
    gemm1_k<<<(N + T - 1) / T, T>>>(x, W1, N);
    {
        long long work = (long long)E * 16;
        scatter1_k<<<(unsigned)((work + T - 1) / T), T>>>(E);
    }
    relu_k<<<(N * 16 + T - 1) / T, T>>>(b1, N * 16);

    // 3. layer 2
    gemm2_k<<<(N + T - 1) / T, T>>>(out, W2, N);
    {
        long long work = (long long)E * 10;
        scatter2_k<<<(unsigned)((work + T - 1) / T), T>>>(out, E);
    }
    finish_k<<<(N + T - 1) / T, T>>>(out, b2, N);
}

// round 5
// speedup vs baseline: 1.8392x; 1.8392x over previous
#include <cuda_runtime.h>

#define MAXN 100000
#define MAXE 1600000
#define SCAN_B 1024

// ---- scratch (device globals; no allocation allowed) ----
__device__ int    g_cnt[MAXN];          // in-degree histogram (excl. self loop)
__device__ int    g_off[MAXN + 1];      // CSR offsets
__device__ int    g_pos[MAXE];          // per-edge slot within its dst bucket
__device__ int    g_bsum[SCAN_B];       // scan block sums
__device__ float  g_dinv[MAXN];
__device__ float2 g_csr[MAXE];          // packed (src as int bits, norm)
__device__ float  g_h1[(size_t)MAXN * 64];   // X@W1
__device__ float  g_h2[(size_t)MAXN * 64];   // relu layer-1 output
__device__ float  g_h3[(size_t)MAXN * 40];   // h2@W2

// ---------------- CSR build ----------------
__global__ void zero_cnt_k(int N) {
    int i = blockIdx.x * blockDim.x + threadIdx.x;
    if (i < N) g_cnt[i] = 0;
}

__global__ void count_k(const int* __restrict__ ei, int E) {
    int i = blockIdx.x * blockDim.x + threadIdx.x;
    if (i >= E) return;
    int d = ei[E + i];
    g_pos[i] = atomicAdd(g_cnt + d, 1);
}

// scan1: per-block exclusive scan of g_cnt (1024 elems/block) -> g_off, block totals
__global__ __launch_bounds__(SCAN_B) void scan1_k(int N) {
    __shared__ int sm[SCAN_B];
    int t = threadIdx.x;
    int i = blockIdx.x * SCAN_B + t;
    int v = (i < N) ? g_cnt[i] : 0;
    sm[t] = v;
    __syncthreads();
#pragma unroll
    for (int o = 1; o < SCAN_B; o <<= 1) {
        int x = (t >= o) ? sm[t - o] : 0;
        __syncthreads();
        sm[t] += x;
        __syncthreads();
    }
    if (i < N) g_off[i] = sm[t] - v;           // exclusive
    if (t == SCAN_B - 1) g_bsum[blockIdx.x] = sm[t];
}

// scan2: exclusive scan of the block sums (single block); also writes g_off[N]=E
__global__ __launch_bounds__(SCAN_B) void scan2_k(int nb, int E) {
    __shared__ int sm[SCAN_B];
    int t = threadIdx.x;
    int v = (t < nb) ? g_bsum[t] : 0;
    sm[t] = v;
    __syncthreads();
#pragma unroll
    for (int o = 1; o < SCAN_B; o <<= 1) {
        int x = (t >= o) ? sm[t - o] : 0;
        __syncthreads();
        sm[t] += x;
        __syncthreads();
    }
    if (t < nb) g_bsum[t] = sm[t] - v;
    if (t == 0) g_off[MAXN < 0 ? 0 : 0] = g_off[0]; // no-op keep compiler honest
    if (t == 0) ((int*)g_off)[/*N slot patched below*/ 0] += 0;
    if (t == 0) {} // g_off[N] written in scan3 (needs N)
}

// scan3: add block offsets; also dinv and g_off[N]
__global__ void scan3_k(int N, int E) {
    int i = blockIdx.x * blockDim.x + threadIdx.x;
    if (i < N) {
        g_off[i] += g_bsum[i >> 10];
        g_dinv[i] = rsqrtf((float)g_cnt[i] + 1.0f);   // +1 self loop
    }
    if (i == 0) g_off[N] = E;
}

// fill CSR: slot = off[dst] + pos[e], store (src, dinv[s]*dinv[d])
__global__ void fill_k(const int* __restrict__ ei, int E) {
    int i = blockIdx.x * blockDim.x + threadIdx.x;
    if (i >= E) return;
    int s = ei[i];
    int d = ei[E + i];
    int slot = g_off[d] + g_pos[i];
    float2 c;
    c.x = __int_as_float(s);
    c.y = g_dinv[s] * g_dinv[d];
    g_csr[slot] = c;
}

// ---------------- GEMM layer 1: g_h1 = X @ W1 ----------------
__global__ __launch_bounds__(256) void gemm1_k(
    const float* __restrict__ X, const float* __restrict__ W, int N)
{
    __shared__ float Ws[128 * 64];
    for (int i = threadIdx.x; i < 128 * 64; i += 256) Ws[i] = W[i];
    __syncthreads();

    int r = blockIdx.x * 256 + threadIdx.x;
    if (r >= N) return;

    float acc[64];
#pragma unroll
    for (int j = 0; j < 64; j++) acc[j] = 0.f;

    const float4* xr = (const float4*)(X + (size_t)r * 128);
#pragma unroll 1
    for (int k4 = 0; k4 < 32; k4++) {
        float4 xv = xr[k4];
        const float* w0 = Ws + (k4 * 4) * 64;
#pragma unroll
        for (int j = 0; j < 64; j++)
            acc[j] += xv.x * w0[j] + xv.y * w0[64 + j] + xv.z * w0[128 + j] + xv.w * w0[192 + j];
    }

    float4* Hp = (float4*)(g_h1 + (size_t)r * 64);
#pragma unroll
    for (int j4 = 0; j4 < 16; j4++)
        Hp[j4] = make_float4(acc[4*j4], acc[4*j4+1], acc[4*j4+2], acc[4*j4+3]);
}

// -------- gather layer 1: h2 = relu( sum_in h1[src]*nrm + h1[n]*dinv^2 + b1 )
// one warp per node; lane owns features [2*lane, 2*lane+1]
__global__ __launch_bounds__(256) void gather1_k(const float* __restrict__ b1, int N)
{
    int wid = (blockIdx.x * 256 + threadIdx.x) >> 5;
    int lane = threadIdx.x & 31;
    if (wid >= N) return;
    int n = wid;

    int beg = g_off[n], end = g_off[n + 1];
    float2 acc0 = make_float2(0.f, 0.f), acc1 = make_float2(0.f, 0.f);
    int e = beg;
    for (; e + 1 < end; e += 2) {
        float2 c0 = g_csr[e], c1 = g_csr[e + 1];
        const float2 v0 = *(const float2*)(g_h1 + (size_t)__float_as_int(c0.x) * 64 + lane * 2);
        const float2 v1 = *(const float2*)(g_h1 + (size_t)__float_as_int(c1.x) * 64 + lane * 2);
        acc0.x += v0.x * c0.y; acc0.y += v0.y * c0.y;
        acc1.x += v1.x * c1.y; acc1.y += v1.y * c1.y;
    }
    if (e < end) {
        float2 c0 = g_csr[e];
        const float2 v0 = *(const float2*)(g_h1 + (size_t)__float_as_int(c0.x) * 64 + lane * 2);
        acc0.x += v0.x * c0.y; acc0.y += v0.y * c0.y;
    }

    float dv = g_dinv[n];
    float sl = dv * dv;
    float2 h = *(const float2*)(g_h1 + (size_t)n * 64 + lane * 2);
    float2 bb = *(const float2*)(b1 + lane * 2);
    float2 o;
    o.x = fmaxf(acc0.x + acc1.x + h.x * sl + bb.x, 0.f);
    o.y = fmaxf(acc0.y + acc1.y + h.y * sl + bb.y, 0.f);
    *(float2*)(g_h2 + (size_t)n * 64 + lane * 2) = o;
}

// ---------------- GEMM layer 2: g_h3 = h2 @ W2 ----------------
__global__ __launch_bounds__(256) void gemm2_k(const float* __restrict__ W, int N)
{
    __shared__ float Ws[64 * 40];
    for (int i = threadIdx.x; i < 64 * 40; i += 256) Ws[i] = W[i];
    __syncthreads();

    int r = blockIdx.x * 256 + threadIdx.x;
    if (r >= N) return;

    float acc[40];
#pragma unroll
    for (int j = 0; j < 40; j++) acc[j] = 0.f;

    const float4* xr = (const float4*)(g_h2 + (size_t)r * 64);
#pragma unroll 1
    for (int k4 = 0; k4 < 16; k4++) {
        float4 xv = xr[k4];
        const float* w0 = Ws + (k4 * 4) * 40;
#pragma unroll
        for (int j = 0; j < 40; j++)
            acc[j] += xv.x * w0[j] + xv.y * w0[40 + j] + xv.z * w0[80 + j] + xv.w * w0[120 + j];
    }

    float4* Hp = (float4*)(g_h3 + (size_t)r * 40);
#pragma unroll
    for (int j4 = 0; j4 < 10; j4++)
        Hp[j4] = make_float4(acc[4*j4], acc[4*j4+1], acc[4*j4+2], acc[4*j4+3]);
}

// -------- gather layer 2 + bias + log_softmax (fused epilogue) --------
// one warp per node; lanes 0..19 own features [2*lane, 2*lane+1] of 40
__global__ __launch_bounds__(256) void gather2_k(float* __restrict__ out,
                                                 const float* __restrict__ b2, int N)
{
    int wid = (blockIdx.x * 256 + threadIdx.x) >> 5;
    int lane = threadIdx.x & 31;
    if (wid >= N) return;
    int n = wid;
    bool act = lane < 20;

    int beg = g_off[n], end = g_off[n + 1];
    float2 acc0 = make_float2(0.f, 0.f), acc1 = make_float2(0.f, 0.f);
    int fo = act ? lane * 2 : 0;
    int e = beg;
    for (; e + 1 < end; e += 2) {
        float2 c0 = g_csr[e], c1 = g_csr[e + 1];
        const float2 v0 = *(const float2*)(g_h3 + (size_t)__float_as_int(c0.x) * 40 + fo);
        const float2 v1 = *(const float2*)(g_h3 + (size_t)__float_as_int(c1.x) * 40 + fo);
        acc0.x += v0.x * c0.y; acc0.y += v0.y * c0.y;
        acc1.x += v1.x * c1.y; acc1.y += v1.y * c1.y;
    }
    if (e < end) {
        float2 c0 = g_csr[e];
        const float2 v0 = *(const float2*)(g_h3 + (size_t)__float_as_int(c0.x) * 40 + fo);
        acc0.x += v0.x * c0.y; acc0.y += v0.y * c0.y;
    }

    float dv = g_dinv[n];
    float sl = dv * dv;
    float2 h = *(const float2*)(g_h3 + (size_t)n * 40 + fo);
    float2 bb = *(const float2*)(b2 + fo);
    float vx = acc0.x + acc1.x + h.x * sl + bb.x;
    float vy = acc0.y + acc1.y + h.y * sl + bb.y;

    // warp log-softmax over 40 values (lanes >= 20 contribute identities)
    float m = act ? fmaxf(vx, vy) : -3.0e38f;
#pragma unroll
    for (int o = 16; o > 0; o >>= 1) m = fmaxf(m, __shfl_xor_sync(0xFFFFFFFFu, m, o));
    float s = act ? (expf(vx - m) + expf(vy - m)) : 0.f;
#pragma unroll
    for (int o = 16; o > 0; o >>= 1) s += __shfl_xor_sync(0xFFFFFFFFu, s, o);
    float lse = m + logf(s);

    if (act)
        *(float2*)(out + (size_t)n * 40 + fo) = make_float2(vx - lse, vy - lse);
}

extern "C" void kernel_launch(void* const* d_in, const int* in_sizes, int n_in,
                              void* d_out, int out_size)
{
    const float* x  = (const float*)d_in[0];
    const int*   ei = (const int*)d_in[1];      // int32 (JAX x64 disabled)
    const float* W1 = (const float*)d_in[2];
    const float* b1 = (const float*)d_in[3];
    const float* W2 = (const float*)d_in[4];
    const float* b2 = (const float*)d_in[5];
    float* out = (float*)d_out;

    int N = in_sizes[0] / 128;
    int E = in_sizes[1] / 2;
    const int T = 256;
    int nb_scan = (N + SCAN_B - 1) / SCAN_B;

    // CSR build
    zero_cnt_k<<<(N + T - 1) / T, T>>>(N);
    count_k<<<(E + T - 1) / T, T>>>(ei, E);
    scan1_k<<<nb_scan, SCAN_B>>>(N);
    scan2_k<<<1, SCAN_B>>>(nb_scan, E);
    scan3_k<<<(N + T - 1) / T, T>>>(N, E);
    fill_k<<<(E + T - 1) / T, T>>>(ei, E);

    // layer 1
    gemm1_k<<<(N + T - 1) / T, T>>>(x, W1, N);
    gather1_k<<<(N * 32 + T - 1) / T, T>>>(b1, N);

    // layer 2
    gemm2_k<<<(N + T - 1) / T, T>>>(W2, N);
    gather2_k<<<(N * 32 + T - 1) / T, T>>>(out, b2, N);
}

// round 6
// speedup vs baseline: 2.0803x; 1.1311x over previous
#include <cuda_runtime.h>

#define MAXN 100000
#define MAXE 1600000
#define SCAN_B 1024

typedef unsigned long long ull;

// ---- scratch (device globals; no allocation allowed) ----
__device__ int    g_cnt[MAXN];          // in-degree histogram (excl. self loop)
__device__ int    g_off[MAXN + 1];      // CSR offsets
__device__ int    g_pos[MAXE];          // per-edge slot within its dst bucket
__device__ int    g_bsum[SCAN_B];       // scan block sums
__device__ float  g_dinv[MAXN];
__device__ float2 g_csr[MAXE];          // packed (src as int bits, norm)
__device__ float  g_h1[(size_t)MAXN * 64];   // X@W1
__device__ float  g_h2[(size_t)MAXN * 64];   // relu layer-1 output
__device__ float  g_h3[(size_t)MAXN * 40];   // h2@W2

// packed f32x2 FMA: d = a*b + d (two fp32 lanes per instruction)
#define FMA2(d, a, b) asm("fma.rn.f32x2 %0, %1, %2, %0;" : "+l"(d) : "l"(a), "l"(b))
#define PACK2(out, lo, hi) asm("mov.b64 %0, {%1, %2};" : "=l"(out) : "f"(lo), "f"(hi))

// ---------------- CSR build ----------------
__global__ void count_k(const int* __restrict__ ei, int E) {
    int i = blockIdx.x * blockDim.x + threadIdx.x;
    if (i >= E) return;
    int d = ei[E + i];
    g_pos[i] = atomicAdd(g_cnt + d, 1);
}

// scan1: per-block exclusive scan of g_cnt (1024/block) -> g_off + block totals
__global__ __launch_bounds__(SCAN_B) void scan1_k(int N) {
    __shared__ int sm[SCAN_B];
    int t = threadIdx.x;
    int i = blockIdx.x * SCAN_B + t;
    int v = (i < N) ? g_cnt[i] : 0;
    sm[t] = v;
    __syncthreads();
#pragma unroll
    for (int o = 1; o < SCAN_B; o <<= 1) {
        int x = (t >= o) ? sm[t - o] : 0;
        __syncthreads();
        sm[t] += x;
        __syncthreads();
    }
    if (i < N) g_off[i] = sm[t] - v;           // exclusive
    if (t == SCAN_B - 1) g_bsum[blockIdx.x] = sm[t];
}

// scan2: exclusive scan of block sums (single block)
__global__ __launch_bounds__(SCAN_B) void scan2_k(int nb) {
    __shared__ int sm[SCAN_B];
    int t = threadIdx.x;
    int v = (t < nb) ? g_bsum[t] : 0;
    sm[t] = v;
    __syncthreads();
#pragma unroll
    for (int o = 1; o < SCAN_B; o <<= 1) {
        int x = (t >= o) ? sm[t - o] : 0;
        __syncthreads();
        sm[t] += x;
        __syncthreads();
    }
    if (t < nb) g_bsum[t] = sm[t] - v;
}

// scan3: add block offsets; dinv; g_off[N]=E
__global__ void scan3_k(int N, int E) {
    int i = blockIdx.x * blockDim.x + threadIdx.x;
    if (i < N) {
        g_off[i] += g_bsum[i >> 10];
        g_dinv[i] = rsqrtf((float)g_cnt[i] + 1.0f);   // +1 self loop
    }
    if (i == 0) g_off[N] = E;
}

// fill CSR: slot = off[dst] + pos[e], store (src, dinv[s]*dinv[d])
__global__ void fill_k(const int* __restrict__ ei, int E) {
    int i = blockIdx.x * blockDim.x + threadIdx.x;
    if (i >= E) return;
    int s = ei[i];
    int d = ei[E + i];
    int slot = g_off[d] + g_pos[i];
    float2 c;
    c.x = __int_as_float(s);
    c.y = g_dinv[s] * g_dinv[d];
    g_csr[slot] = c;
}

// ---------------- GEMM layer 1: g_h1 = X @ W1 (f32x2 packed) ----------------
__global__ __launch_bounds__(256) void gemm1_k(
    const float* __restrict__ X, const float* __restrict__ W, int N)
{
    __shared__ __align__(16) float Ws[128 * 64];
    for (int i = threadIdx.x; i < 128 * 64; i += 256) Ws[i] = W[i];
    __syncthreads();

    int r = blockIdx.x * 256 + threadIdx.x;
    if (r >= N) return;

    ull acc[32];
#pragma unroll
    for (int j = 0; j < 32; j++) acc[j] = 0ULL;

    const float4* xr = (const float4*)(X + (size_t)r * 128);
#pragma unroll 1
    for (int k4 = 0; k4 < 32; k4++) {
        float4 xv = xr[k4];
        ull xa, xb, xc, xd;
        PACK2(xa, xv.x, xv.x); PACK2(xb, xv.y, xv.y);
        PACK2(xc, xv.z, xv.z); PACK2(xd, xv.w, xv.w);
        const ulonglong2* w0 = (const ulonglong2*)(Ws + (k4 * 4 + 0) * 64);
        const ulonglong2* w1 = (const ulonglong2*)(Ws + (k4 * 4 + 1) * 64);
        const ulonglong2* w2 = (const ulonglong2*)(Ws + (k4 * 4 + 2) * 64);
        const ulonglong2* w3 = (const ulonglong2*)(Ws + (k4 * 4 + 3) * 64);
#pragma unroll
        for (int j = 0; j < 16; j++) {       // j covers 4 floats = 2 pairs
            ulonglong2 a0 = w0[j]; FMA2(acc[2*j], xa, a0.x); FMA2(acc[2*j+1], xa, a0.y);
            ulonglong2 a1 = w1[j]; FMA2(acc[2*j], xb, a1.x); FMA2(acc[2*j+1], xb, a1.y);
            ulonglong2 a2 = w2[j]; FMA2(acc[2*j], xc, a2.x); FMA2(acc[2*j+1], xc, a2.y);
            ulonglong2 a3 = w3[j]; FMA2(acc[2*j], xd, a3.x); FMA2(acc[2*j+1], xd, a3.y);
        }
    }

    ulonglong2* Hp = (ulonglong2*)(g_h1 + (size_t)r * 64);
#pragma unroll
    for (int j = 0; j < 16; j++) {
        ulonglong2 v; v.x = acc[2*j]; v.y = acc[2*j+1];
        Hp[j] = v;
    }
}

// -------- gather layer 1: h2 = relu( sum_in h1[src]*nrm + h1[n]*dinv^2 + b1 )
// one warp per node; half-warps process alternating edges, lane owns 4 feats
__global__ __launch_bounds__(256) void gather1_k(const float* __restrict__ b1, int N)
{
    int wid = (blockIdx.x * 256 + threadIdx.x) >> 5;
    int lane = threadIdx.x & 31;
    if (wid >= N) return;
    int n = wid;
    int half = lane >> 4;     // 0 or 1
    int hl = lane & 15;       // feature group: feats [hl*4, hl*4+4)

    int beg = g_off[n], end = g_off[n + 1];
    float4 acc = make_float4(0.f, 0.f, 0.f, 0.f);
    int e = beg + half;
    // unroll 2: up to 4 edges in flight per warp
    for (; e + 2 < end; e += 4) {
        float2 c0 = g_csr[e], c1 = g_csr[e + 2];
        float4 v0 = *(const float4*)(g_h1 + (size_t)__float_as_int(c0.x) * 64 + hl * 4);
        float4 v1 = *(const float4*)(g_h1 + (size_t)__float_as_int(c1.x) * 64 + hl * 4);
        acc.x += v0.x * c0.y + v1.x * c1.y;
        acc.y += v0.y * c0.y + v1.y * c1.y;
        acc.z += v0.z * c0.y + v1.z * c1.y;
        acc.w += v0.w * c0.y + v1.w * c1.y;
    }
    if (e < end) {
        float2 c0 = g_csr[e];
        float4 v0 = *(const float4*)(g_h1 + (size_t)__float_as_int(c0.x) * 64 + hl * 4);
        acc.x += v0.x * c0.y; acc.y += v0.y * c0.y;
        acc.z += v0.z * c0.y; acc.w += v0.w * c0.y;
    }

    // combine the two halves (xor 16 swaps halves; both get the sum)
    acc.x += __shfl_xor_sync(0xFFFFFFFFu, acc.x, 16);
    acc.y += __shfl_xor_sync(0xFFFFFFFFu, acc.y, 16);
    acc.z += __shfl_xor_sync(0xFFFFFFFFu, acc.z, 16);
    acc.w += __shfl_xor_sync(0xFFFFFFFFu, acc.w, 16);

    if (half == 0) {
        float dv = g_dinv[n];
        float sl = dv * dv;
        float4 h = *(const float4*)(g_h1 + (size_t)n * 64 + hl * 4);
        float4 bb = *(const float4*)(b1 + hl * 4);
        float4 o;
        o.x = fmaxf(acc.x + h.x * sl + bb.x, 0.f);
        o.y = fmaxf(acc.y + h.y * sl + bb.y, 0.f);
        o.z = fmaxf(acc.z + h.z * sl + bb.z, 0.f);
        o.w = fmaxf(acc.w + h.w * sl + bb.w, 0.f);
        *(float4*)(g_h2 + (size_t)n * 64 + hl * 4) = o;
    }
}

// ---------------- GEMM layer 2: g_h3 = h2 @ W2 (f32x2 packed) ----------------
__global__ __launch_bounds__(256) void gemm2_k(const float* __restrict__ W, int N)
{
    __shared__ __align__(16) float Ws[64 * 40];
    for (int i = threadIdx.x; i < 64 * 40; i += 256) Ws[i] = W[i];
    __syncthreads();

    int r = blockIdx.x * 256 + threadIdx.x;
    if (r >= N) return;

    ull acc[20];
#pragma unroll
    for (int j = 0; j < 20; j++) acc[j] = 0ULL;

    const float4* xr = (const float4*)(g_h2 + (size_t)r * 64);
#pragma unroll 1
    for (int k4 = 0; k4 < 16; k4++) {
        float4 xv = xr[k4];
        ull xa, xb, xc, xd;
        PACK2(xa, xv.x, xv.x); PACK2(xb, xv.y, xv.y);
        PACK2(xc, xv.z, xv.z); PACK2(xd, xv.w, xv.w);
        const ulonglong2* w0 = (const ulonglong2*)(Ws + (k4 * 4 + 0) * 40);
        const ulonglong2* w1 = (const ulonglong2*)(Ws + (k4 * 4 + 1) * 40);
        const ulonglong2* w2 = (const ulonglong2*)(Ws + (k4 * 4 + 2) * 40);
        const ulonglong2* w3 = (const ulonglong2*)(Ws + (k4 * 4 + 3) * 40);
#pragma unroll
        for (int j = 0; j < 10; j++) {
            ulonglong2 a0 = w0[j]; FMA2(acc[2*j], xa, a0.x); FMA2(acc[2*j+1], xa, a0.y);
            ulonglong2 a1 = w1[j]; FMA2(acc[2*j], xb, a1.x); FMA2(acc[2*j+1], xb, a1.y);
            ulonglong2 a2 = w2[j]; FMA2(acc[2*j], xc, a2.x); FMA2(acc[2*j+1], xc, a2.y);
            ulonglong2 a3 = w3[j]; FMA2(acc[2*j], xd, a3.x); FMA2(acc[2*j+1], xd, a3.y);
        }
    }

    ulonglong2* Hp = (ulonglong2*)(g_h3 + (size_t)r * 40);
#pragma unroll
    for (int j = 0; j < 10; j++) {
        ulonglong2 v; v.x = acc[2*j]; v.y = acc[2*j+1];
        Hp[j] = v;
    }
}

// -------- gather layer 2 + bias + log_softmax (fused epilogue) --------
// one warp per node; lanes 0..19 own features [2*lane, 2*lane+1] of 40
__global__ __launch_bounds__(256) void gather2_k(float* __restrict__ out,
                                                 const float* __restrict__ b2, int N)
{
    int wid = (blockIdx.x * 256 + threadIdx.x) >> 5;
    int lane = threadIdx.x & 31;
    if (wid >= N) return;
    int n = wid;
    bool act = lane < 20;
    int fo = act ? lane * 2 : 0;

    int beg = g_off[n], end = g_off[n + 1];
    float2 a0 = make_float2(0.f, 0.f), a1 = make_float2(0.f, 0.f);
    float2 a2 = make_float2(0.f, 0.f), a3 = make_float2(0.f, 0.f);
    int e = beg;
    for (; e + 3 < end; e += 4) {
        float2 c0 = g_csr[e],     c1 = g_csr[e + 1];
        float2 c2 = g_csr[e + 2], c3 = g_csr[e + 3];
        float2 v0 = *(const float2*)(g_h3 + (size_t)__float_as_int(c0.x) * 40 + fo);
        float2 v1 = *(const float2*)(g_h3 + (size_t)__float_as_int(c1.x) * 40 + fo);
        float2 v2 = *(const float2*)(g_h3 + (size_t)__float_as_int(c2.x) * 40 + fo);
        float2 v3 = *(const float2*)(g_h3 + (size_t)__float_as_int(c3.x) * 40 + fo);
        a0.x += v0.x * c0.y; a0.y += v0.y * c0.y;
        a1.x += v1.x * c1.y; a1.y += v1.y * c1.y;
        a2.x += v2.x * c2.y; a2.y += v2.y * c2.y;
        a3.x += v3.x * c3.y; a3.y += v3.y * c3.y;
    }
    for (; e < end; e++) {
        float2 c0 = g_csr[e];
        float2 v0 = *(const float2*)(g_h3 + (size_t)__float_as_int(c0.x) * 40 + fo);
        a0.x += v0.x * c0.y; a0.y += v0.y * c0.y;
    }

    float dv = g_dinv[n];
    float sl = dv * dv;
    float2 h = *(const float2*)(g_h3 + (size_t)n * 40 + fo);
    float2 bb = *(const float2*)(b2 + fo);
    float vx = a0.x + a1.x + a2.x + a3.x + h.x * sl + bb.x;
    float vy = a0.y + a1.y + a2.y + a3.y + h.y * sl + bb.y;

    // warp log-softmax over 40 values (lanes >= 20 contribute identities)
    float m = act ? fmaxf(vx, vy) : -3.0e38f;
#pragma unroll
    for (int o = 16; o > 0; o >>= 1) m = fmaxf(m, __shfl_xor_sync(0xFFFFFFFFu, m, o));
    float s = act ? (expf(vx - m) + expf(vy - m)) : 0.f;
#pragma unroll
    for (int o = 16; o > 0; o >>= 1) s += __shfl_xor_sync(0xFFFFFFFFu, s, o);
    float lse = m + logf(s);

    if (act)
        *(float2*)(out + (size_t)n * 40 + fo) = make_float2(vx - lse, vy - lse);
}

extern "C" void kernel_launch(void* const* d_in, const int* in_sizes, int n_in,
                              void* d_out, int out_size)
{
    const float* x  = (const float*)d_in[0];
    const int*   ei = (const int*)d_in[1];      // int32 (JAX x64 disabled)
    const float* W1 = (const float*)d_in[2];
    const float* b1 = (const float*)d_in[3];
    const float* W2 = (const float*)d_in[4];
    const float* b2 = (const float*)d_in[5];
    float* out = (float*)d_out;

    int N = in_sizes[0] / 128;
    int E = in_sizes[1] / 2;
    const int T = 256;
    int nb_scan = (N + SCAN_B - 1) / SCAN_B;

    // CSR build
    void* cnt_ptr = 0;
    cudaGetSymbolAddress(&cnt_ptr, g_cnt);
    cudaMemsetAsync(cnt_ptr, 0, (size_t)N * sizeof(int));
    count_k<<<(E + T - 1) / T, T>>>(ei, E);
    scan1_k<<<nb_scan, SCAN_B>>>(N);
    scan2_k<<<1, SCAN_B>>>(nb_scan);
    scan3_k<<<(N + T - 1) / T, T>>>(N, E);
    fill_k<<<(E + T - 1) / T, T>>>(ei, E);

    // layer 1
    gemm1_k<<<(N + T - 1) / T, T>>>(x, W1, N);
    gather1_k<<<(N * 32 + T - 1) / T, T>>>(b1, N);

    // layer 2
    gemm2_k<<<(N + T - 1) / T, T>>>(W2, N);
    gather2_k<<<(N * 32 + T - 1) / T, T>>>(out, b2, N);
}